// round 14
// baseline (speedup 1.0000x reference)
#include <cuda_runtime.h>
#include <cuda_bf16.h>
#include <math.h>
#include <stdint.h>

// ---------------- problem constants ----------------
#define NATOM 20000
#define NATOMP 20096              // padded to 157*128
#define MNBR  12
#define NM    (NATOM*MNBR)        // 240000
#define NBRF  41
#define IN2   297
#define NCONV 3
#define BN_EPS 1e-5f
#define NCHUNKS 5                 // W K-chunks (0,1 self / 2,3 nbr / 4 nf)
#define NTILES  (NM/128)          // 1875
#define NSTILES (NATOMP/128)      // 157
#define TSTRIDE 72                // smem row stride in bf16 (144B, conflict-free ldmatrix)
#define TILE_B  (128*TSTRIDE*2)   // 18432 B per 128-row tile
#define WHALF_B (64*TSTRIDE*2)    // 9216 B per 64-row W tile
#define STAGE_B (3*TILE_B)        // atom-kernel stage (Ah, Al, Wh 128 rows)

// prep_all segment sizes
#define SEG_NF   (NM*64)
#define SEG_W    (4*NCHUNKS*256*64)
#define SEG_EMB  (92*128)
#define SEG_ST   1280
#define PREP_TOT (SEG_NF + SEG_W + SEG_EMB + SEG_ST)

// ---------------- device scratch ----------------
__device__ float d_af[NATOM*128];
__device__ float d_g [NM*256];
__device__ float d_y [NATOMP*256];            // self-part per-atom GEMM
__device__ float d_z [NATOMP*256];            // nbr-part per-atom GEMM
__device__ float d_s [NATOM*128];
__device__ float d_dist[NM];
__device__ float d_embWt[92*128];
__device__ float d_stats[1280];
__device__ __nv_bfloat16 d_afh[NATOMP*128];   // zero-init padding rows
__device__ __nv_bfloat16 d_afl[NATOMP*128];
__device__ __nv_bfloat16 d_nfh[NM*64];
__device__ __nv_bfloat16 d_nfl[NM*64];
__device__ __nv_bfloat16 d_wh[4*NCHUNKS*256*64];   // [slot][chunk][row 256][64]

// ---------------- PTX helpers (portable: sm_80+ / sm_75+) ----------------
__device__ __forceinline__ uint32_t smem_u32(const void* p){
    uint32_t a; asm("{ .reg .u64 t; cvta.to.shared.u64 t, %1; cvt.u32.u64 %0, t; }" : "=r"(a) : "l"(p));
    return a;
}
__device__ __forceinline__ void cp16(uint32_t dst, const void* src){
    asm volatile("cp.async.cg.shared.global [%0], [%1], 16;" :: "r"(dst), "l"(src));
}
__device__ __forceinline__ void cp_commit(){
    asm volatile("cp.async.commit_group;" ::: "memory");
}
__device__ __forceinline__ void ldsm_x4(uint32_t* r, uint32_t addr){
    asm volatile("ldmatrix.sync.aligned.m8n8.x4.shared.b16 {%0,%1,%2,%3}, [%4];"
        : "=r"(r[0]), "=r"(r[1]), "=r"(r[2]), "=r"(r[3]) : "r"(addr));
}
__device__ __forceinline__ void mma16816(float* c, const uint32_t* a, uint32_t b0, uint32_t b1){
    asm volatile("mma.sync.aligned.m16n8k16.row.col.f32.bf16.bf16.f32 "
        "{%0,%1,%2,%3}, {%4,%5,%6,%7}, {%8,%9}, {%0,%1,%2,%3};"
        : "+f"(c[0]), "+f"(c[1]), "+f"(c[2]), "+f"(c[3])
        : "r"(a[0]), "r"(a[1]), "r"(a[2]), "r"(a[3]), "r"(b0), "r"(b1));
}

// ---------------- helpers ----------------
__device__ __forceinline__ float softplusf(float x){
    return fmaxf(x, 0.f) + log1pf(expf(-fabsf(x)));
}

// ---------------- fused prep: nf split + W bf16 + emb transpose + stats zero ----------------
__global__ void k_prep_all(const float* __restrict__ nf,
                           const float* __restrict__ convs_W, const float* __restrict__ dist_W,
                           const float* __restrict__ const_W, const float* __restrict__ emb_W,
                           __nv_bfloat16* __restrict__ nfh, __nv_bfloat16* __restrict__ nfl,
                           __nv_bfloat16* __restrict__ wh, float* __restrict__ embWt,
                           float* __restrict__ stats){
    size_t i = (size_t)blockIdx.x*256 + threadIdx.x;
    if (i < SEG_NF){
        size_t r = i >> 6; int k = (int)(i & 63);
        float v = (k < NBRF) ? nf[r*NBRF + k] : 0.f;
        __nv_bfloat16 h = __float2bfloat16(v);
        nfh[i] = h;
        nfl[i] = __float2bfloat16(v - __bfloat162float(h));
        return;
    }
    i -= SEG_NF;
    if (i < SEG_W){
        int k = (int)(i & 63);
        int row = (int)((i >> 6) & 255);
        int cs = (int)(i >> 14);
        int c = cs % 5, slot = cs / 5;
        int gk = c*64 + k;
        float v = 0.f;
        if (gk < IN2){
            if (slot < 3) v = convs_W[(size_t)slot*256*IN2 + (size_t)row*IN2 + gk];
            else          v = (row < 128) ? dist_W[(size_t)row*IN2 + gk]
                                          : const_W[(size_t)(row-128)*IN2 + gk];
        }
        wh[i] = __float2bfloat16(v);
        return;
    }
    i -= SEG_W;
    if (i < SEG_EMB){
        int f = (int)(i >> 7), o = (int)(i & 127);
        embWt[i] = emb_W[o*92 + f];
        return;
    }
    i -= SEG_EMB;
    if (i < SEG_ST) stats[i] = 0.f;
}

__global__ void k_zero(float* __restrict__ p, int n){
    int i = blockIdx.x*256 + threadIdx.x;
    if (i < n) p[i] = 0.f;
}

// ---------------- embedding (fused af->bf16 hi/lo split) ----------------
__global__ void k_embed(const float* __restrict__ atom_fea, const float* __restrict__ embWt,
                        const float* __restrict__ emb_b, float* __restrict__ af,
                        __nv_bfloat16* __restrict__ afh, __nv_bfloat16* __restrict__ afl){
    __shared__ float sf[16*92];
    int nb = blockIdx.x * 16;
    int a  = threadIdx.x;
    for (int e = threadIdx.x; e < 16*92; e += 128){
        int i = e / 92, k = e - i*92;
        sf[e] = atom_fea[(nb + i)*92 + k];
    }
    __syncthreads();
    float acc[16];
    #pragma unroll
    for (int i = 0; i < 16; ++i) acc[i] = 0.f;
    for (int k = 0; k < 92; ++k){
        float w = embWt[k*128 + a];
        #pragma unroll
        for (int i = 0; i < 16; ++i) acc[i] += sf[i*92 + k] * w;
    }
    float b = emb_b[a];
    #pragma unroll
    for (int i = 0; i < 16; ++i){
        float v = acc[i] + b;
        int o = (nb + i)*128 + a;
        af[o] = v;
        __nv_bfloat16 h = __float2bfloat16(v);
        afh[o] = h;
        afl[o] = __float2bfloat16(v - __bfloat162float(h));
    }
}

// ---------------- PBC distance ----------------
__global__ void k_distance(const float* __restrict__ pos, const float* __restrict__ off,
                           const float* __restrict__ cells, const int* __restrict__ idx,
                           float* __restrict__ dist){
    int r = blockIdx.x*256 + threadIdx.x;
    if (r >= NM) return;
    int n = r / MNBR;
    int j = idx[r];
    float o0 = off[r*3+0], o1 = off[r*3+1], o2 = off[r*3+2];
    float acc = 1e-12f;
    #pragma unroll
    for (int d = 0; d < 3; ++d){
        float v = pos[j*3+d] + o0*cells[d] + o1*cells[3+d] + o2*cells[6+d] - pos[n*3+d];
        acc += v*v;
    }
    dist[r] = sqrtf(acc);
}

// ---------------- full-width chunk compute (atom kernel: 128x128 tile) ----------------
__device__ __forceinline__ void mma_chunk(uint32_t ubase, int wm, int wn, int lane,
                                          float c[2][8][4]){
    const uint32_t uAh = ubase;
    const uint32_t uAl = ubase + TILE_B;
    const uint32_t uWh = ubase + 2*TILE_B;
    #pragma unroll
    for (int ks = 0; ks < 4; ++ks){
        const int k0 = ks*16;
        const uint32_t aoff = (uint32_t)((wm + (lane & 15))*TSTRIDE + k0 + (lane >> 4)*8) * 2;
        const uint32_t boff = (uint32_t)((wn + ((lane >> 4) << 3) + (lane & 7))*TSTRIDE
                                         + k0 + ((lane >> 3) & 1)*8) * 2;
        uint32_t ah[2][4], al[2][4], bh[4][4];
        ldsm_x4(ah[0], uAh + aoff);
        ldsm_x4(ah[1], uAh + aoff + 16*TSTRIDE*2);
        #pragma unroll
        for (int nt = 0; nt < 4; ++nt) ldsm_x4(bh[nt], uWh + boff + nt*16*TSTRIDE*2);
        #pragma unroll
        for (int mt = 0; mt < 2; ++mt)
            #pragma unroll
            for (int n8 = 0; n8 < 8; ++n8)
                mma16816(c[mt][n8], ah[mt], bh[n8>>1][(n8&1)*2], bh[n8>>1][(n8&1)*2+1]);
        ldsm_x4(al[0], uAl + aoff);
        ldsm_x4(al[1], uAl + aoff + 16*TSTRIDE*2);
        #pragma unroll
        for (int mt = 0; mt < 2; ++mt)
            #pragma unroll
            for (int n8 = 0; n8 < 8; ++n8)
                mma16816(c[mt][n8], al[mt], bh[n8>>1][(n8&1)*2], bh[n8>>1][(n8&1)*2+1]);
    }
}

// ---------------- per-atom GEMMs: Y = af @ Wself^T, Z = af @ Wnbr^T ----------------
__global__ void __launch_bounds__(256, 2)
k_mma_atom(const __nv_bfloat16* __restrict__ afh, const __nv_bfloat16* __restrict__ afl,
           const __nv_bfloat16* __restrict__ wh, float* __restrict__ Y, float* __restrict__ Z)
{
    extern __shared__ __nv_bfloat16 smem[];
    const uint32_t sb = smem_u32(smem);

    const int tid  = threadIdx.x;
    const int wid  = tid >> 5, lane = tid & 31;
    const int zsel  = blockIdx.x >> 1;
    const int nhalf = blockIdx.x & 1;
    const int r0    = blockIdx.y * 128;
    const int wm = (wid & 3) * 32;
    const int wn = (wid >> 2) * 64;
    const int c8 = (tid & 7) * 8;
    float* __restrict__ out = zsel ? Z : Y;

    float c[2][8][4];
    #pragma unroll
    for (int a = 0; a < 2; ++a)
        #pragma unroll
        for (int b = 0; b < 8; ++b)
            #pragma unroll
            for (int q = 0; q < 4; ++q) c[a][b][q] = 0.f;

    auto load_chunk = [&](int cc, int stg){
        const uint32_t ub = sb + stg*STAGE_B;
        #pragma unroll
        for (int j = 0; j < 4; ++j){
            int m = (tid >> 3) + j*32;
            uint32_t doff = (uint32_t)(m*TSTRIDE + c8) * 2;
            size_t o = (size_t)(r0 + m)*128 + cc*64 + c8;
            cp16(ub + doff, afh + o);
            cp16(ub + TILE_B + doff, afl + o);
        }
        const size_t wb = (size_t)(zsel*2 + cc)*16384 + (size_t)nhalf*128*64;
        #pragma unroll
        for (int j = 0; j < 4; ++j){
            int rr = (tid >> 3) + j*32;
            uint32_t doff = (uint32_t)(rr*TSTRIDE + c8) * 2;
            cp16(ub + 2*TILE_B + doff, wh + wb + (size_t)rr*64 + c8);
        }
        cp_commit();
    };

    load_chunk(0, 0);
    #pragma unroll
    for (int cc = 0; cc < 2; ++cc){
        if (cc + 1 < 2){
            load_chunk(cc + 1, (cc + 1) & 1);
            asm volatile("cp.async.wait_group 1;" ::: "memory");
        } else {
            asm volatile("cp.async.wait_group 0;" ::: "memory");
        }
        __syncthreads();
        mma_chunk(sb + (cc & 1)*STAGE_B, wm, wn, lane, c);
        if (cc + 1 < 2) __syncthreads();
    }

    #pragma unroll
    for (int mt = 0; mt < 2; ++mt){
        #pragma unroll
        for (int j = 0; j < 8; ++j){
            int lcol = wn + j*8 + (lane & 3)*2;
            int row  = r0 + wm + mt*16 + (lane >> 2);
            *reinterpret_cast<float2*>(&out[(size_t)row*256     + nhalf*128 + lcol]) =
                make_float2(c[mt][j][0], c[mt][j][1]);
            *reinterpret_cast<float2*>(&out[(size_t)(row+8)*256 + nhalf*128 + lcol]) =
                make_float2(c[mt][j][2], c[mt][j][3]);
        }
    }
}

// ---------------- main per-edge GEMM: 128x64 tile for occupancy ----------------
// grid dim3(4, NTILES): nq = col quarter (0..3 of 256). Warp tile 32x32.
// C[r, nq*64+n] = Y[r/12] + Z[idx[r]] + nf-part + bias; fused bn stats.
__global__ void __launch_bounds__(256, 3)
k_mma(const __nv_bfloat16* __restrict__ nfh, const __nv_bfloat16* __restrict__ nfl,
      const __nv_bfloat16* __restrict__ wh,
      const float* __restrict__ Y, const float* __restrict__ Z,
      const int* __restrict__ idx, const float* __restrict__ b0, const float* __restrict__ b1,
      float* __restrict__ C, float* __restrict__ st)
{
    extern __shared__ __nv_bfloat16 smem[];
    const uint32_t sb = smem_u32(smem);
    const uint32_t uWh = sb + 2*TILE_B;

    const int tid  = threadIdx.x;
    const int wid  = tid >> 5, lane = tid & 31;
    const int nq   = blockIdx.x;        // 0..3 (64-col quarter)
    const int r0   = blockIdx.y * 128;
    const int wm = (wid & 3) * 32;      // warp row base
    const int wn = (wid >> 2) * 32;     // warp col base within 64
    const int c8 = (tid & 7) * 8;

    const int row_b = r0 + wm + (lane >> 2);
    int selfi[4], nbri[4];
    #pragma unroll
    for (int j = 0; j < 4; ++j){
        int r = row_b + (j >> 1)*16 + (j & 1)*8;   // mt*16 + {0,8}
        selfi[j] = r / MNBR;
        nbri[j]  = idx[r];
    }

    float c[2][4][4];
    #pragma unroll
    for (int a = 0; a < 2; ++a)
        #pragma unroll
        for (int b = 0; b < 4; ++b)
            #pragma unroll
            for (int q = 0; q < 4; ++q) c[a][b][q] = 0.f;

    // --- load nf tile (h/l, 128 rows) + W quarter (64 rows of chunk 4) ---
    {
        #pragma unroll
        for (int j = 0; j < 4; ++j){
            int m = (tid >> 3) + j*32;
            uint32_t doff = (uint32_t)(m*TSTRIDE + c8) * 2;
            size_t o = (size_t)(r0 + m)*64 + c8;
            cp16(sb + doff, nfh + o);
            cp16(sb + TILE_B + doff, nfl + o);
        }
        const size_t wb = (size_t)4*16384 + (size_t)nq*64*64;
        #pragma unroll
        for (int j = 0; j < 2; ++j){
            int rr = (tid >> 3) + j*32;
            uint32_t doff = (uint32_t)(rr*TSTRIDE + c8) * 2;
            cp16(uWh + doff, wh + wb + (size_t)rr*64 + c8);
        }
        cp_commit();
        asm volatile("cp.async.wait_group 0;" ::: "memory");
        __syncthreads();
    }

    // --- compute: 4 k16 steps, terms AhBh + AlBh, 32x32 warp tile ---
    #pragma unroll
    for (int ks = 0; ks < 4; ++ks){
        const int k0 = ks*16;
        const uint32_t aoff = (uint32_t)((wm + (lane & 15))*TSTRIDE + k0 + (lane >> 4)*8) * 2;
        const uint32_t boff = (uint32_t)((wn + ((lane >> 4) << 3) + (lane & 7))*TSTRIDE
                                         + k0 + ((lane >> 3) & 1)*8) * 2;
        uint32_t ah[2][4], al[2][4], bh[2][4];
        ldsm_x4(ah[0], sb + aoff);
        ldsm_x4(ah[1], sb + aoff + 16*TSTRIDE*2);
        #pragma unroll
        for (int nt = 0; nt < 2; ++nt) ldsm_x4(bh[nt], uWh + boff + nt*16*TSTRIDE*2);
        #pragma unroll
        for (int mt = 0; mt < 2; ++mt)
            #pragma unroll
            for (int n8 = 0; n8 < 4; ++n8)
                mma16816(c[mt][n8], ah[mt], bh[n8>>1][(n8&1)*2], bh[n8>>1][(n8&1)*2+1]);
        ldsm_x4(al[0], sb + TILE_B + aoff);
        ldsm_x4(al[1], sb + TILE_B + aoff + 16*TSTRIDE*2);
        #pragma unroll
        for (int mt = 0; mt < 2; ++mt)
            #pragma unroll
            for (int n8 = 0; n8 < 4; ++n8)
                mma16816(c[mt][n8], al[mt], bh[n8>>1][(n8&1)*2], bh[n8>>1][(n8&1)*2+1]);
    }

    // --- epilogue: add Y (self) + Z (nbr) + bias, fused bn stats, stores ---
    const float* __restrict__ bias = (nq < 2) ? (b0 + nq*64) : (b1 + (nq - 2)*64);
    #pragma unroll
    for (int mt = 0; mt < 2; ++mt){
        #pragma unroll
        for (int j = 0; j < 4; ++j){
            int lcol = wn + j*8 + (lane & 3)*2;
            size_t co = (size_t)(nq*64 + lcol);
            float2 bv = *reinterpret_cast<const float2*>(&bias[lcol]);
            float2 y0 = *reinterpret_cast<const float2*>(&Y[(size_t)selfi[mt*2]*256 + co]);
            float2 z0 = *reinterpret_cast<const float2*>(&Z[(size_t)nbri[mt*2]*256 + co]);
            float2 y1 = *reinterpret_cast<const float2*>(&Y[(size_t)selfi[mt*2+1]*256 + co]);
            float2 z1 = *reinterpret_cast<const float2*>(&Z[(size_t)nbri[mt*2+1]*256 + co]);
            c[mt][j][0] += bv.x + y0.x + z0.x; c[mt][j][1] += bv.y + y0.y + z0.y;
            c[mt][j][2] += bv.x + y1.x + z1.x; c[mt][j][3] += bv.y + y1.y + z1.y;
        }
    }
    #pragma unroll
    for (int j = 0; j < 4; ++j){
        float s0 = c[0][j][0] + c[0][j][2] + c[1][j][0] + c[1][j][2];
        float q0 = c[0][j][0]*c[0][j][0] + c[0][j][2]*c[0][j][2]
                 + c[1][j][0]*c[1][j][0] + c[1][j][2]*c[1][j][2];
        float s1 = c[0][j][1] + c[0][j][3] + c[1][j][1] + c[1][j][3];
        float q1 = c[0][j][1]*c[0][j][1] + c[0][j][3]*c[0][j][3]
                 + c[1][j][1]*c[1][j][1] + c[1][j][3]*c[1][j][3];
        #pragma unroll
        for (int o = 4; o < 32; o <<= 1){
            s0 += __shfl_xor_sync(0xFFFFFFFFu, s0, o);
            q0 += __shfl_xor_sync(0xFFFFFFFFu, q0, o);
            s1 += __shfl_xor_sync(0xFFFFFFFFu, s1, o);
            q1 += __shfl_xor_sync(0xFFFFFFFFu, q1, o);
        }
        if (lane < 4){
            int gc = nq*64 + wn + j*8 + lane*2;
            atomicAdd(&st[gc],       s0);
            atomicAdd(&st[256 + gc], q0);
            atomicAdd(&st[gc + 1],       s1);
            atomicAdd(&st[256 + gc + 1], q1);
        }
    }
    #pragma unroll
    for (int mt = 0; mt < 2; ++mt){
        #pragma unroll
        for (int j = 0; j < 4; ++j){
            int lcol = wn + j*8 + (lane & 3)*2;
            int row  = r0 + wm + mt*16 + (lane >> 2);
            *reinterpret_cast<float2*>(&C[(size_t)row*256     + nq*64 + lcol]) =
                make_float2(c[mt][j][0], c[mt][j][1]);
            *reinterpret_cast<float2*>(&C[(size_t)(row+8)*256 + nq*64 + lcol]) =
                make_float2(c[mt][j][2], c[mt][j][3]);
        }
    }
}

// ---------------- conv gate + sum over neighbors (2 atoms per CTA) ----------------
__global__ void k_gate_sum(const float* __restrict__ g, const float* __restrict__ st,
                           const float* __restrict__ bn1_g, const float* __restrict__ bn1_b,
                           float* __restrict__ s){
    const int n = blockIdx.x*2 + (threadIdx.x >> 7);
    const int a = threadIdx.x & 127;
    const float invNM = 1.f / (float)NM;
    float mu  = st[a]       * invNM;
    float var = st[256 + a] * invNM - mu*mu;
    float scF = bn1_g[a] * rsqrtf(var + BN_EPS);
    float shF = bn1_b[a] - mu*scF;
    mu  = st[128 + a] * invNM;
    var = st[384 + a] * invNM - mu*mu;
    float scC = bn1_g[128+a] * rsqrtf(var + BN_EPS);
    float shC = bn1_b[128+a] - mu*scC;

    float acc = 0.f;
    const size_t base = (size_t)n*MNBR*256;
    #pragma unroll
    for (int m = 0; m < MNBR; ++m){
        float gf = g[base + m*256 + a];
        float gc = g[base + m*256 + 128 + a];
        float f = 1.f / (1.f + expf(-(scF*gf + shF)));
        float c = scC*gc + shC;
        c = c >= 0.f ? c : 0.01f*c;
        acc += f * c;
    }
    s[n*128 + a] = acc;
}

// ---------------- column stats over s (128 cols, for bn2) ----------------
__global__ void k_colstats(const float* __restrict__ s, float* __restrict__ stats){
    const int a  = threadIdx.x;
    const int r0 = blockIdx.x * 200;
    float sum = 0.f, sq = 0.f;
    for (int i = 0; i < 200; ++i){
        float v = s[(r0 + i)*128 + a];
        sum += v; sq += v*v;
    }
    atomicAdd(&stats[a], sum);
    atomicAdd(&stats[128 + a], sq);
}

// ---------------- residual update: af = leaky(af + bn2(s)) + bf16 split ----------------
__global__ void k_af_update(float* __restrict__ af, const float* __restrict__ s,
                            const float* __restrict__ statsB,
                            const float* __restrict__ g2, const float* __restrict__ b2,
                            __nv_bfloat16* __restrict__ afh, __nv_bfloat16* __restrict__ afl){
    int i = blockIdx.x*256 + threadIdx.x;
    if (i >= NATOM*128) return;
    int a = i & 127;
    const float invN = 1.f / (float)NATOM;
    float mu  = statsB[a]     * invN;
    float var = statsB[128+a] * invN - mu*mu;
    float sc = g2[a] * rsqrtf(var + BN_EPS);
    float sh = b2[a] - mu*sc;
    float v = af[i] + sc*s[i] + sh;
    v = v >= 0.f ? v : 0.01f*v;
    af[i] = v;
    __nv_bfloat16 h = __float2bfloat16(v);
    afh[i] = h;
    afl[i] = __float2bfloat16(v - __bfloat162float(h));
}

// ---------------- heads epilogue ----------------
__global__ void k_head_final(const float* __restrict__ g, const float* __restrict__ st,
                             const float* __restrict__ dbn_g, const float* __restrict__ dbn_b,
                             const float* __restrict__ cbn_g, const float* __restrict__ cbn_b,
                             const float* __restrict__ d2W, const float* __restrict__ d2b,
                             const float* __restrict__ c2W, const float* __restrict__ c2b,
                             const float* __restrict__ dist, float* __restrict__ out){
    __shared__ float sdc[4*128];
    const int tid = threadIdx.x;
    const float invNM = 1.f / (float)NM;
    if (tid < 128){
        float mu  = st[tid]*invNM;
        float var = st[256+tid]*invNM - mu*mu;
        float sc  = dbn_g[tid] * rsqrtf(var + BN_EPS);
        sdc[tid] = sc; sdc[128+tid] = dbn_b[tid] - mu*sc;
        mu  = st[128+tid]*invNM;
        var = st[384+tid]*invNM - mu*mu;
        sc  = cbn_g[tid] * rsqrtf(var + BN_EPS);
        sdc[256+tid] = sc; sdc[384+tid] = cbn_b[tid] - mu*sc;
    }
    __syncthreads();
    const int warp = tid >> 5, lane = tid & 31;
    const int r = blockIdx.x*8 + warp;
    float accd = 0.f, accc = 0.f;
    #pragma unroll
    for (int k = 0; k < 4; ++k){
        int c = lane + 32*k;
        float vd = g[(size_t)r*256 + c];
        float h  = sdc[c]*vd + sdc[128+c];
        h = h >= 0.f ? h : 0.01f*h;
        accd += h * d2W[c];
        float vc = g[(size_t)r*256 + 128 + c];
        float hc = softplusf(sdc[256+c]*vc + sdc[384+c]);
        accc += hc * c2W[c];
    }
    #pragma unroll
    for (int o = 16; o > 0; o >>= 1){
        accd += __shfl_xor_sync(0xFFFFFFFFu, accd, o);
        accc += __shfl_xor_sync(0xFFFFFFFFu, accc, o);
    }
    if (lane == 0){
        float bd = accd + d2b[0] + dist[r];
        bd = bd >= 0.f ? bd : 0.01f*bd;
        float bc = softplusf(accc + c2b[0]);
        out[r*2 + 0] = bd;
        out[r*2 + 1] = bc;
    }
}

// ---------------- launch ----------------
#define ATOM_SMEM (2*STAGE_B)             // 110592 B (2-stage pipeline)
#define MAIN_SMEM (2*TILE_B + WHALF_B)    // 46080 B

extern "C" void kernel_launch(void* const* d_in, const int* in_sizes, int n_in,
                              void* d_out, int out_size){
    (void)n_in; (void)out_size;
    const bool dictOrder = (in_sizes[5] == NM);
    const int base = dictOrder ? 6 : 5;
    const float* atom_fea = (const float*)d_in[0];
    const float* nbr_fea  = (const float*)d_in[1];
    const float* nbr_off  = (const float*)d_in[2];
    const float* atom_pos = (const float*)d_in[3];
    const float* cells    = (const float*)d_in[4];
    const int*   nbr_idx  = (const int*)d_in[dictOrder ? 5 : 25];
    const float* emb_W    = (const float*)d_in[base + 0];
    const float* emb_b    = (const float*)d_in[base + 1];
    const float* convs_W  = (const float*)d_in[base + 2];
    const float* convs_b  = (const float*)d_in[base + 3];
    const float* bn1_g    = (const float*)d_in[base + 4];
    const float* bn1_b    = (const float*)d_in[base + 5];
    const float* bn2_g    = (const float*)d_in[base + 6];
    const float* bn2_b    = (const float*)d_in[base + 7];
    const float* dist_W   = (const float*)d_in[base + 8];
    const float* dist_b   = (const float*)d_in[base + 9];
    const float* dbn_g    = (const float*)d_in[base + 10];
    const float* dbn_b    = (const float*)d_in[base + 11];
    const float* d2W      = (const float*)d_in[base + 12];
    const float* d2b      = (const float*)d_in[base + 13];
    const float* const_W  = (const float*)d_in[base + 14];
    const float* const_b  = (const float*)d_in[base + 15];
    const float* cbn_g    = (const float*)d_in[base + 16];
    const float* cbn_b    = (const float*)d_in[base + 17];
    const float* c2W      = (const float*)d_in[base + 18];
    const float* c2b      = (const float*)d_in[base + 19];
    float* out = (float*)d_out;

    float *p_af, *p_g, *p_y, *p_z, *p_s, *p_dist, *p_ewt, *p_stats;
    __nv_bfloat16 *p_afh, *p_afl, *p_nfh, *p_nfl, *p_wh;
    cudaGetSymbolAddress((void**)&p_af,   d_af);
    cudaGetSymbolAddress((void**)&p_g,    d_g);
    cudaGetSymbolAddress((void**)&p_y,    d_y);
    cudaGetSymbolAddress((void**)&p_z,    d_z);
    cudaGetSymbolAddress((void**)&p_s,    d_s);
    cudaGetSymbolAddress((void**)&p_dist, d_dist);
    cudaGetSymbolAddress((void**)&p_ewt,  d_embWt);
    cudaGetSymbolAddress((void**)&p_stats,d_stats);
    cudaGetSymbolAddress((void**)&p_afh,  d_afh);
    cudaGetSymbolAddress((void**)&p_afl,  d_afl);
    cudaGetSymbolAddress((void**)&p_nfh,  d_nfh);
    cudaGetSymbolAddress((void**)&p_nfl,  d_nfl);
    cudaGetSymbolAddress((void**)&p_wh,   d_wh);

    cudaFuncSetAttribute(k_mma,      cudaFuncAttributeMaxDynamicSharedMemorySize, MAIN_SMEM);
    cudaFuncSetAttribute(k_mma_atom, cudaFuncAttributeMaxDynamicSharedMemorySize, ATOM_SMEM);

    // slot 1: fused prep
    k_prep_all<<<(PREP_TOT + 255)/256, 256>>>(nbr_fea, convs_W, dist_W, const_W, emb_W,
                                              p_nfh, p_nfl, p_wh, p_ewt, p_stats);
    // slot 2: embedding
    k_embed<<<NATOM/16, 128>>>(atom_fea, p_ewt, emb_b, p_af, p_afh, p_afl);
    // slot 3: conv0 per-atom GEMMs
    k_mma_atom<<<dim3(4, NSTILES), 256, ATOM_SMEM>>>(p_afh, p_afl, p_wh, p_y, p_z);
    // slot 4: conv0 main GEMM  <-- profiled by ncu
    k_mma<<<dim3(4, NTILES), 256, MAIN_SMEM>>>(p_nfh, p_nfl, p_wh, p_y, p_z,
                                               nbr_idx, convs_b, convs_b + 128,
                                               p_g, p_stats);
    k_distance<<<(NM + 255)/256, 256>>>(atom_pos, nbr_off, cells, nbr_idx, p_dist);

    // --- conv layers ---
    for (int i = 0; i < NCONV; ++i){
        if (i > 0){
            k_zero<<<3, 256>>>(p_stats, 768);
            k_mma_atom<<<dim3(4, NSTILES), 256, ATOM_SMEM>>>(p_afh, p_afl,
                                                             p_wh + (size_t)i*NCHUNKS*16384, p_y, p_z);
            k_mma<<<dim3(4, NTILES), 256, MAIN_SMEM>>>(p_nfh, p_nfl,
                                                       p_wh + (size_t)i*NCHUNKS*16384, p_y, p_z,
                                                       nbr_idx, convs_b + i*256, convs_b + i*256 + 128,
                                                       p_g, p_stats);
        }
        k_gate_sum<<<NATOM/2, 256>>>(p_g, p_stats, bn1_g + i*256, bn1_b + i*256, p_s);
        k_colstats<<<NATOM/200, 128>>>(p_s, p_stats + 512);
        k_af_update<<<(NATOM*128 + 255)/256, 256>>>(p_af, p_s, p_stats + 512,
                                                    bn2_g + i*128, bn2_b + i*128, p_afh, p_afl);
    }

    // --- heads ---
    k_zero<<<2, 256>>>(p_stats, 512);
    k_mma_atom<<<dim3(4, NSTILES), 256, ATOM_SMEM>>>(p_afh, p_afl,
                                                     p_wh + (size_t)3*NCHUNKS*16384, p_y, p_z);
    k_mma<<<dim3(4, NTILES), 256, MAIN_SMEM>>>(p_nfh, p_nfl,
                                               p_wh + (size_t)3*NCHUNKS*16384, p_y, p_z,
                                               nbr_idx, dist_b, const_b, p_g, p_stats);
    k_head_final<<<NM/8, 256>>>(p_g, p_stats,
                                dbn_g, dbn_b, cbn_g, cbn_b,
                                d2W, d2b, c2W, c2b, p_dist, out);
}

// round 15
// speedup vs baseline: 1.0634x; 1.0634x over previous
#include <cuda_runtime.h>
#include <cuda_bf16.h>
#include <math.h>
#include <stdint.h>

// ---------------- problem constants ----------------
#define NATOM 20000
#define NATOMP 20096              // padded to 157*128
#define MNBR  12
#define NM    (NATOM*MNBR)        // 240000
#define NBRF  41
#define IN2   297
#define NCONV 3
#define BN_EPS 1e-5f
#define NCHUNKS 5                 // W K-chunks (0,1 self / 2,3 nbr / 4 nf)
#define NTILES  (NM/128)          // 1875
#define NSTILES (NATOMP/128)      // 157
#define TSTRIDE 72                // smem row stride in bf16 (144B, conflict-free ldmatrix)
#define TILE_B  (128*TSTRIDE*2)   // 18432 B per tile
#define STAGE_B (3*TILE_B)        // 55296 B per stage (Ah, Al, Wh)

// prep_all segment sizes
#define SEG_NF   (NM*64)
#define SEG_W    (4*NCHUNKS*256*64)
#define SEG_EMB  (92*128)
#define SEG_ST   1280
#define PREP_TOT (SEG_NF + SEG_W + SEG_EMB + SEG_ST)

// ---------------- device scratch ----------------
__device__ float d_af[NATOM*128];
__device__ __nv_bfloat16 d_g[NM*256];         // g intermediate stored bf16 (halves traffic)
__device__ float d_y [NATOMP*256];            // self-part per-atom GEMM
__device__ float d_z [NATOMP*256];            // nbr-part per-atom GEMM
__device__ float d_s [NATOM*128];
__device__ float d_dist[NM];
__device__ float d_embWt[92*128];
__device__ float d_stats[1280];
__device__ __nv_bfloat16 d_afh[NATOMP*128];   // zero-init padding rows
__device__ __nv_bfloat16 d_afl[NATOMP*128];
__device__ __nv_bfloat16 d_nfh[NM*64];
__device__ __nv_bfloat16 d_nfl[NM*64];
__device__ __nv_bfloat16 d_wh[4*NCHUNKS*256*64];   // [slot][chunk][row 256][64]

// ---------------- PTX helpers (portable: sm_80+ / sm_75+) ----------------
__device__ __forceinline__ uint32_t smem_u32(const void* p){
    uint32_t a; asm("{ .reg .u64 t; cvta.to.shared.u64 t, %1; cvt.u32.u64 %0, t; }" : "=r"(a) : "l"(p));
    return a;
}
__device__ __forceinline__ void cp16(uint32_t dst, const void* src){
    asm volatile("cp.async.cg.shared.global [%0], [%1], 16;" :: "r"(dst), "l"(src));
}
__device__ __forceinline__ void cp_commit(){
    asm volatile("cp.async.commit_group;" ::: "memory");
}
__device__ __forceinline__ void ldsm_x4(uint32_t* r, uint32_t addr){
    asm volatile("ldmatrix.sync.aligned.m8n8.x4.shared.b16 {%0,%1,%2,%3}, [%4];"
        : "=r"(r[0]), "=r"(r[1]), "=r"(r[2]), "=r"(r[3]) : "r"(addr));
}
__device__ __forceinline__ void mma16816(float* c, const uint32_t* a, uint32_t b0, uint32_t b1){
    asm volatile("mma.sync.aligned.m16n8k16.row.col.f32.bf16.bf16.f32 "
        "{%0,%1,%2,%3}, {%4,%5,%6,%7}, {%8,%9}, {%0,%1,%2,%3};"
        : "+f"(c[0]), "+f"(c[1]), "+f"(c[2]), "+f"(c[3])
        : "r"(a[0]), "r"(a[1]), "r"(a[2]), "r"(a[3]), "r"(b0), "r"(b1));
}

// ---------------- helpers ----------------
__device__ __forceinline__ float softplusf(float x){
    return fmaxf(x, 0.f) + log1pf(expf(-fabsf(x)));
}

// ---------------- fused prep: nf split + W bf16 + emb transpose + stats zero ----------------
__global__ void k_prep_all(const float* __restrict__ nf,
                           const float* __restrict__ convs_W, const float* __restrict__ dist_W,
                           const float* __restrict__ const_W, const float* __restrict__ emb_W,
                           __nv_bfloat16* __restrict__ nfh, __nv_bfloat16* __restrict__ nfl,
                           __nv_bfloat16* __restrict__ wh, float* __restrict__ embWt,
                           float* __restrict__ stats){
    size_t i = (size_t)blockIdx.x*256 + threadIdx.x;
    if (i < SEG_NF){
        size_t r = i >> 6; int k = (int)(i & 63);
        float v = (k < NBRF) ? nf[r*NBRF + k] : 0.f;
        __nv_bfloat16 h = __float2bfloat16(v);
        nfh[i] = h;
        nfl[i] = __float2bfloat16(v - __bfloat162float(h));
        return;
    }
    i -= SEG_NF;
    if (i < SEG_W){
        int k = (int)(i & 63);
        int row = (int)((i >> 6) & 255);
        int cs = (int)(i >> 14);
        int c = cs % 5, slot = cs / 5;
        int gk = c*64 + k;
        float v = 0.f;
        if (gk < IN2){
            if (slot < 3) v = convs_W[(size_t)slot*256*IN2 + (size_t)row*IN2 + gk];
            else          v = (row < 128) ? dist_W[(size_t)row*IN2 + gk]
                                          : const_W[(size_t)(row-128)*IN2 + gk];
        }
        wh[i] = __float2bfloat16(v);
        return;
    }
    i -= SEG_W;
    if (i < SEG_EMB){
        int f = (int)(i >> 7), o = (int)(i & 127);
        embWt[i] = emb_W[o*92 + f];
        return;
    }
    i -= SEG_EMB;
    if (i < SEG_ST) stats[i] = 0.f;
}

__global__ void k_zero(float* __restrict__ p, int n){
    int i = blockIdx.x*256 + threadIdx.x;
    if (i < n) p[i] = 0.f;
}

// ---------------- embedding (fused af->bf16 hi/lo split) ----------------
__global__ void k_embed(const float* __restrict__ atom_fea, const float* __restrict__ embWt,
                        const float* __restrict__ emb_b, float* __restrict__ af,
                        __nv_bfloat16* __restrict__ afh, __nv_bfloat16* __restrict__ afl){
    __shared__ float sf[16*92];
    int nb = blockIdx.x * 16;
    int a  = threadIdx.x;
    for (int e = threadIdx.x; e < 16*92; e += 128){
        int i = e / 92, k = e - i*92;
        sf[e] = atom_fea[(nb + i)*92 + k];
    }
    __syncthreads();
    float acc[16];
    #pragma unroll
    for (int i = 0; i < 16; ++i) acc[i] = 0.f;
    for (int k = 0; k < 92; ++k){
        float w = embWt[k*128 + a];
        #pragma unroll
        for (int i = 0; i < 16; ++i) acc[i] += sf[i*92 + k] * w;
    }
    float b = emb_b[a];
    #pragma unroll
    for (int i = 0; i < 16; ++i){
        float v = acc[i] + b;
        int o = (nb + i)*128 + a;
        af[o] = v;
        __nv_bfloat16 h = __float2bfloat16(v);
        afh[o] = h;
        afl[o] = __float2bfloat16(v - __bfloat162float(h));
    }
}

// ---------------- PBC distance ----------------
__global__ void k_distance(const float* __restrict__ pos, const float* __restrict__ off,
                           const float* __restrict__ cells, const int* __restrict__ idx,
                           float* __restrict__ dist){
    int r = blockIdx.x*256 + threadIdx.x;
    if (r >= NM) return;
    int n = r / MNBR;
    int j = idx[r];
    float o0 = off[r*3+0], o1 = off[r*3+1], o2 = off[r*3+2];
    float acc = 1e-12f;
    #pragma unroll
    for (int d = 0; d < 3; ++d){
        float v = pos[j*3+d] + o0*cells[d] + o1*cells[3+d] + o2*cells[6+d] - pos[n*3+d];
        acc += v*v;
    }
    dist[r] = sqrtf(acc);
}

// ---------------- shared compute step (one 64-K chunk from a given stage) ----------------
__device__ __forceinline__ void mma_chunk(uint32_t ubase, int wm, int wn, int lane,
                                          float c[2][8][4]){
    const uint32_t uAh = ubase;
    const uint32_t uAl = ubase + TILE_B;
    const uint32_t uWh = ubase + 2*TILE_B;
    #pragma unroll
    for (int ks = 0; ks < 4; ++ks){
        const int k0 = ks*16;
        const uint32_t aoff = (uint32_t)((wm + (lane & 15))*TSTRIDE + k0 + (lane >> 4)*8) * 2;
        const uint32_t boff = (uint32_t)((wn + ((lane >> 4) << 3) + (lane & 7))*TSTRIDE
                                         + k0 + ((lane >> 3) & 1)*8) * 2;
        uint32_t ah[2][4], al[2][4], bh[4][4];
        ldsm_x4(ah[0], uAh + aoff);
        ldsm_x4(ah[1], uAh + aoff + 16*TSTRIDE*2);
        #pragma unroll
        for (int nt = 0; nt < 4; ++nt) ldsm_x4(bh[nt], uWh + boff + nt*16*TSTRIDE*2);
        #pragma unroll
        for (int mt = 0; mt < 2; ++mt)
            #pragma unroll
            for (int n8 = 0; n8 < 8; ++n8)
                mma16816(c[mt][n8], ah[mt], bh[n8>>1][(n8&1)*2], bh[n8>>1][(n8&1)*2+1]);
        ldsm_x4(al[0], uAl + aoff);
        ldsm_x4(al[1], uAl + aoff + 16*TSTRIDE*2);
        #pragma unroll
        for (int mt = 0; mt < 2; ++mt)
            #pragma unroll
            for (int n8 = 0; n8 < 8; ++n8)
                mma16816(c[mt][n8], al[mt], bh[n8>>1][(n8&1)*2], bh[n8>>1][(n8&1)*2+1]);
    }
}

// ---------------- per-atom GEMMs: Y = af @ Wself^T, Z = af @ Wnbr^T ----------------
__global__ void __launch_bounds__(256, 2)
k_mma_atom(const __nv_bfloat16* __restrict__ afh, const __nv_bfloat16* __restrict__ afl,
           const __nv_bfloat16* __restrict__ wh, float* __restrict__ Y, float* __restrict__ Z)
{
    extern __shared__ __nv_bfloat16 smem[];
    const uint32_t sb = smem_u32(smem);

    const int tid  = threadIdx.x;
    const int wid  = tid >> 5, lane = tid & 31;
    const int zsel  = blockIdx.x >> 1;
    const int nhalf = blockIdx.x & 1;
    const int r0    = blockIdx.y * 128;
    const int wm = (wid & 3) * 32;
    const int wn = (wid >> 2) * 64;
    const int c8 = (tid & 7) * 8;
    float* __restrict__ out = zsel ? Z : Y;

    float c[2][8][4];
    #pragma unroll
    for (int a = 0; a < 2; ++a)
        #pragma unroll
        for (int b = 0; b < 8; ++b)
            #pragma unroll
            for (int q = 0; q < 4; ++q) c[a][b][q] = 0.f;

    auto load_chunk = [&](int cc, int stg){
        const uint32_t ub = sb + stg*STAGE_B;
        #pragma unroll
        for (int j = 0; j < 4; ++j){
            int m = (tid >> 3) + j*32;
            uint32_t doff = (uint32_t)(m*TSTRIDE + c8) * 2;
            size_t o = (size_t)(r0 + m)*128 + cc*64 + c8;
            cp16(ub + doff, afh + o);
            cp16(ub + TILE_B + doff, afl + o);
        }
        const size_t wb = (size_t)(zsel*2 + cc)*16384 + (size_t)nhalf*128*64;
        #pragma unroll
        for (int j = 0; j < 4; ++j){
            int rr = (tid >> 3) + j*32;
            uint32_t doff = (uint32_t)(rr*TSTRIDE + c8) * 2;
            cp16(ub + 2*TILE_B + doff, wh + wb + (size_t)rr*64 + c8);
        }
        cp_commit();
    };

    load_chunk(0, 0);
    #pragma unroll
    for (int cc = 0; cc < 2; ++cc){
        if (cc + 1 < 2){
            load_chunk(cc + 1, (cc + 1) & 1);
            asm volatile("cp.async.wait_group 1;" ::: "memory");
        } else {
            asm volatile("cp.async.wait_group 0;" ::: "memory");
        }
        __syncthreads();
        mma_chunk(sb + (cc & 1)*STAGE_B, wm, wn, lane, c);
        if (cc + 1 < 2) __syncthreads();
    }

    #pragma unroll
    for (int mt = 0; mt < 2; ++mt){
        #pragma unroll
        for (int j = 0; j < 8; ++j){
            int lcol = wn + j*8 + (lane & 3)*2;
            int row  = r0 + wm + mt*16 + (lane >> 2);
            *reinterpret_cast<float2*>(&out[(size_t)row*256     + nhalf*128 + lcol]) =
                make_float2(c[mt][j][0], c[mt][j][1]);
            *reinterpret_cast<float2*>(&out[(size_t)(row+8)*256 + nhalf*128 + lcol]) =
                make_float2(c[mt][j][2], c[mt][j][3]);
        }
    }
}

// ---------------- main per-edge GEMM: nbr_fea chunk + direct Y/Z gather epilogue ----------------
// 128x128 tile (R13 shape). C stored bf16; stats computed from fp32 registers.
__global__ void __launch_bounds__(256, 2)
k_mma(const __nv_bfloat16* __restrict__ nfh, const __nv_bfloat16* __restrict__ nfl,
      const __nv_bfloat16* __restrict__ wh,
      const float* __restrict__ Y, const float* __restrict__ Z,
      const int* __restrict__ idx, const float* __restrict__ b0, const float* __restrict__ b1,
      __nv_bfloat16* __restrict__ C, float* __restrict__ st)
{
    extern __shared__ __nv_bfloat16 smem[];
    const uint32_t sb = smem_u32(smem);

    const int tid  = threadIdx.x;
    const int wid  = tid >> 5, lane = tid & 31;
    const int nhalf = blockIdx.x;
    const int r0    = blockIdx.y * 128;
    const int wm = (wid & 3) * 32;
    const int wn = (wid >> 2) * 64;
    const int c8 = (tid & 7) * 8;

    const int row_b = r0 + wm + (lane >> 2);
    int selfi[4], nbri[4];
    #pragma unroll
    for (int j = 0; j < 4; ++j){
        int r = row_b + j*8;
        selfi[j] = r / MNBR;
        nbri[j]  = idx[r];
    }

    float c[2][8][4];
    #pragma unroll
    for (int a = 0; a < 2; ++a)
        #pragma unroll
        for (int b = 0; b < 8; ++b)
            #pragma unroll
            for (int q = 0; q < 4; ++q) c[a][b][q] = 0.f;

    // --- load nf tile (h/l) + W chunk 4 ---
    {
        #pragma unroll
        for (int j = 0; j < 4; ++j){
            int m = (tid >> 3) + j*32;
            uint32_t doff = (uint32_t)(m*TSTRIDE + c8) * 2;
            size_t o = (size_t)(r0 + m)*64 + c8;
            cp16(sb + doff, nfh + o);
            cp16(sb + TILE_B + doff, nfl + o);
        }
        const size_t wb = (size_t)4*16384 + (size_t)nhalf*128*64;
        #pragma unroll
        for (int j = 0; j < 4; ++j){
            int rr = (tid >> 3) + j*32;
            uint32_t doff = (uint32_t)(rr*TSTRIDE + c8) * 2;
            cp16(sb + 2*TILE_B + doff, wh + wb + (size_t)rr*64 + c8);
        }
        cp_commit();
        asm volatile("cp.async.wait_group 0;" ::: "memory");
        __syncthreads();
    }
    mma_chunk(sb, wm, wn, lane, c);

    // --- epilogue: add Y (self) + Z (nbr) + bias, fused bn stats, bf16 stores ---
    const float* __restrict__ bias = nhalf ? b1 : b0;
    #pragma unroll
    for (int mt = 0; mt < 2; ++mt){
        #pragma unroll
        for (int j = 0; j < 8; ++j){
            int lcol = wn + j*8 + (lane & 3)*2;
            size_t co = (size_t)(nhalf*128 + lcol);
            float2 bv = *reinterpret_cast<const float2*>(&bias[lcol]);
            float2 y0 = *reinterpret_cast<const float2*>(&Y[(size_t)selfi[mt*2]*256 + co]);
            float2 z0 = *reinterpret_cast<const float2*>(&Z[(size_t)nbri[mt*2]*256 + co]);
            float2 y1 = *reinterpret_cast<const float2*>(&Y[(size_t)selfi[mt*2+1]*256 + co]);
            float2 z1 = *reinterpret_cast<const float2*>(&Z[(size_t)nbri[mt*2+1]*256 + co]);
            c[mt][j][0] += bv.x + y0.x + z0.x; c[mt][j][1] += bv.y + y0.y + z0.y;
            c[mt][j][2] += bv.x + y1.x + z1.x; c[mt][j][3] += bv.y + y1.y + z1.y;
        }
    }
    #pragma unroll
    for (int j = 0; j < 8; ++j){
        float s0 = c[0][j][0] + c[0][j][2] + c[1][j][0] + c[1][j][2];
        float q0 = c[0][j][0]*c[0][j][0] + c[0][j][2]*c[0][j][2]
                 + c[1][j][0]*c[1][j][0] + c[1][j][2]*c[1][j][2];
        float s1 = c[0][j][1] + c[0][j][3] + c[1][j][1] + c[1][j][3];
        float q1 = c[0][j][1]*c[0][j][1] + c[0][j][3]*c[0][j][3]
                 + c[1][j][1]*c[1][j][1] + c[1][j][3]*c[1][j][3];
        #pragma unroll
        for (int o = 4; o < 32; o <<= 1){
            s0 += __shfl_xor_sync(0xFFFFFFFFu, s0, o);
            q0 += __shfl_xor_sync(0xFFFFFFFFu, q0, o);
            s1 += __shfl_xor_sync(0xFFFFFFFFu, s1, o);
            q1 += __shfl_xor_sync(0xFFFFFFFFu, q1, o);
        }
        if (lane < 4){
            int gc = nhalf*128 + wn + j*8 + lane*2;
            atomicAdd(&st[gc],       s0);
            atomicAdd(&st[256 + gc], q0);
            atomicAdd(&st[gc + 1],       s1);
            atomicAdd(&st[256 + gc + 1], q1);
        }
    }
    #pragma unroll
    for (int mt = 0; mt < 2; ++mt){
        #pragma unroll
        for (int j = 0; j < 8; ++j){
            int lcol = wn + j*8 + (lane & 3)*2;
            int row  = r0 + wm + mt*16 + (lane >> 2);
            *reinterpret_cast<__nv_bfloat162*>(&C[(size_t)row*256     + nhalf*128 + lcol]) =
                __floats2bfloat162_rn(c[mt][j][0], c[mt][j][1]);
            *reinterpret_cast<__nv_bfloat162*>(&C[(size_t)(row+8)*256 + nhalf*128 + lcol]) =
                __floats2bfloat162_rn(c[mt][j][2], c[mt][j][3]);
        }
    }
}

// ---------------- conv gate + sum over neighbors (2 atoms per CTA, bf16 g) ----------------
__global__ void k_gate_sum(const __nv_bfloat16* __restrict__ g, const float* __restrict__ st,
                           const float* __restrict__ bn1_g, const float* __restrict__ bn1_b,
                           float* __restrict__ s){
    const int n = blockIdx.x*2 + (threadIdx.x >> 7);
    const int a = threadIdx.x & 127;
    const float invNM = 1.f / (float)NM;
    float mu  = st[a]       * invNM;
    float var = st[256 + a] * invNM - mu*mu;
    float scF = bn1_g[a] * rsqrtf(var + BN_EPS);
    float shF = bn1_b[a] - mu*scF;
    mu  = st[128 + a] * invNM;
    var = st[384 + a] * invNM - mu*mu;
    float scC = bn1_g[128+a] * rsqrtf(var + BN_EPS);
    float shC = bn1_b[128+a] - mu*scC;

    float acc = 0.f;
    const size_t base = (size_t)n*MNBR*256;
    #pragma unroll
    for (int m = 0; m < MNBR; ++m){
        float gf = __bfloat162float(g[base + m*256 + a]);
        float gc = __bfloat162float(g[base + m*256 + 128 + a]);
        float f = 1.f / (1.f + expf(-(scF*gf + shF)));
        float c = scC*gc + shC;
        c = c >= 0.f ? c : 0.01f*c;
        acc += f * c;
    }
    s[n*128 + a] = acc;
}

// ---------------- column stats over s (128 cols, for bn2) ----------------
__global__ void k_colstats(const float* __restrict__ s, float* __restrict__ stats){
    const int a  = threadIdx.x;
    const int r0 = blockIdx.x * 200;
    float sum = 0.f, sq = 0.f;
    for (int i = 0; i < 200; ++i){
        float v = s[(r0 + i)*128 + a];
        sum += v; sq += v*v;
    }
    atomicAdd(&stats[a], sum);
    atomicAdd(&stats[128 + a], sq);
}

// ---------------- residual update: af = leaky(af + bn2(s)) + bf16 split ----------------
__global__ void k_af_update(float* __restrict__ af, const float* __restrict__ s,
                            const float* __restrict__ statsB,
                            const float* __restrict__ g2, const float* __restrict__ b2,
                            __nv_bfloat16* __restrict__ afh, __nv_bfloat16* __restrict__ afl){
    int i = blockIdx.x*256 + threadIdx.x;
    if (i >= NATOM*128) return;
    int a = i & 127;
    const float invN = 1.f / (float)NATOM;
    float mu  = statsB[a]     * invN;
    float var = statsB[128+a] * invN - mu*mu;
    float sc = g2[a] * rsqrtf(var + BN_EPS);
    float sh = b2[a] - mu*sc;
    float v = af[i] + sc*s[i] + sh;
    v = v >= 0.f ? v : 0.01f*v;
    af[i] = v;
    __nv_bfloat16 h = __float2bfloat16(v);
    afh[i] = h;
    afl[i] = __float2bfloat16(v - __bfloat162float(h));
}

// ---------------- heads epilogue (bf16 g) ----------------
__global__ void k_head_final(const __nv_bfloat16* __restrict__ g, const float* __restrict__ st,
                             const float* __restrict__ dbn_g, const float* __restrict__ dbn_b,
                             const float* __restrict__ cbn_g, const float* __restrict__ cbn_b,
                             const float* __restrict__ d2W, const float* __restrict__ d2b,
                             const float* __restrict__ c2W, const float* __restrict__ c2b,
                             const float* __restrict__ dist, float* __restrict__ out){
    __shared__ float sdc[4*128];
    const int tid = threadIdx.x;
    const float invNM = 1.f / (float)NM;
    if (tid < 128){
        float mu  = st[tid]*invNM;
        float var = st[256+tid]*invNM - mu*mu;
        float sc  = dbn_g[tid] * rsqrtf(var + BN_EPS);
        sdc[tid] = sc; sdc[128+tid] = dbn_b[tid] - mu*sc;
        mu  = st[128+tid]*invNM;
        var = st[384+tid]*invNM - mu*mu;
        sc  = cbn_g[tid] * rsqrtf(var + BN_EPS);
        sdc[256+tid] = sc; sdc[384+tid] = cbn_b[tid] - mu*sc;
    }
    __syncthreads();
    const int warp = tid >> 5, lane = tid & 31;
    const int r = blockIdx.x*8 + warp;
    float accd = 0.f, accc = 0.f;
    #pragma unroll
    for (int k = 0; k < 4; ++k){
        int c = lane + 32*k;
        float vd = __bfloat162float(g[(size_t)r*256 + c]);
        float h  = sdc[c]*vd + sdc[128+c];
        h = h >= 0.f ? h : 0.01f*h;
        accd += h * d2W[c];
        float vc = __bfloat162float(g[(size_t)r*256 + 128 + c]);
        float hc = softplusf(sdc[256+c]*vc + sdc[384+c]);
        accc += hc * c2W[c];
    }
    #pragma unroll
    for (int o = 16; o > 0; o >>= 1){
        accd += __shfl_xor_sync(0xFFFFFFFFu, accd, o);
        accc += __shfl_xor_sync(0xFFFFFFFFu, accc, o);
    }
    if (lane == 0){
        float bd = accd + d2b[0] + dist[r];
        bd = bd >= 0.f ? bd : 0.01f*bd;
        float bc = softplusf(accc + c2b[0]);
        out[r*2 + 0] = bd;
        out[r*2 + 1] = bc;
    }
}

// ---------------- launch ----------------
#define ATOM_SMEM (2*STAGE_B)   // 110592 B (2-stage pipeline)
#define MAIN_SMEM (STAGE_B)     // 55296 B (single chunk)

extern "C" void kernel_launch(void* const* d_in, const int* in_sizes, int n_in,
                              void* d_out, int out_size){
    (void)n_in; (void)out_size;
    const bool dictOrder = (in_sizes[5] == NM);
    const int base = dictOrder ? 6 : 5;
    const float* atom_fea = (const float*)d_in[0];
    const float* nbr_fea  = (const float*)d_in[1];
    const float* nbr_off  = (const float*)d_in[2];
    const float* atom_pos = (const float*)d_in[3];
    const float* cells    = (const float*)d_in[4];
    const int*   nbr_idx  = (const int*)d_in[dictOrder ? 5 : 25];
    const float* emb_W    = (const float*)d_in[base + 0];
    const float* emb_b    = (const float*)d_in[base + 1];
    const float* convs_W  = (const float*)d_in[base + 2];
    const float* convs_b  = (const float*)d_in[base + 3];
    const float* bn1_g    = (const float*)d_in[base + 4];
    const float* bn1_b    = (const float*)d_in[base + 5];
    const float* bn2_g    = (const float*)d_in[base + 6];
    const float* bn2_b    = (const float*)d_in[base + 7];
    const float* dist_W   = (const float*)d_in[base + 8];
    const float* dist_b   = (const float*)d_in[base + 9];
    const float* dbn_g    = (const float*)d_in[base + 10];
    const float* dbn_b    = (const float*)d_in[base + 11];
    const float* d2W      = (const float*)d_in[base + 12];
    const float* d2b      = (const float*)d_in[base + 13];
    const float* const_W  = (const float*)d_in[base + 14];
    const float* const_b  = (const float*)d_in[base + 15];
    const float* cbn_g    = (const float*)d_in[base + 16];
    const float* cbn_b    = (const float*)d_in[base + 17];
    const float* c2W      = (const float*)d_in[base + 18];
    const float* c2b      = (const float*)d_in[base + 19];
    float* out = (float*)d_out;

    float *p_af, *p_y, *p_z, *p_s, *p_dist, *p_ewt, *p_stats;
    __nv_bfloat16 *p_g, *p_afh, *p_afl, *p_nfh, *p_nfl, *p_wh;
    cudaGetSymbolAddress((void**)&p_af,   d_af);
    cudaGetSymbolAddress((void**)&p_g,    d_g);
    cudaGetSymbolAddress((void**)&p_y,    d_y);
    cudaGetSymbolAddress((void**)&p_z,    d_z);
    cudaGetSymbolAddress((void**)&p_s,    d_s);
    cudaGetSymbolAddress((void**)&p_dist, d_dist);
    cudaGetSymbolAddress((void**)&p_ewt,  d_embWt);
    cudaGetSymbolAddress((void**)&p_stats,d_stats);
    cudaGetSymbolAddress((void**)&p_afh,  d_afh);
    cudaGetSymbolAddress((void**)&p_afl,  d_afl);
    cudaGetSymbolAddress((void**)&p_nfh,  d_nfh);
    cudaGetSymbolAddress((void**)&p_nfl,  d_nfl);
    cudaGetSymbolAddress((void**)&p_wh,   d_wh);

    cudaFuncSetAttribute(k_mma,      cudaFuncAttributeMaxDynamicSharedMemorySize, MAIN_SMEM);
    cudaFuncSetAttribute(k_mma_atom, cudaFuncAttributeMaxDynamicSharedMemorySize, ATOM_SMEM);

    // slot 1: fused prep
    k_prep_all<<<(PREP_TOT + 255)/256, 256>>>(nbr_fea, convs_W, dist_W, const_W, emb_W,
                                              p_nfh, p_nfl, p_wh, p_ewt, p_stats);
    // slot 2: embedding
    k_embed<<<NATOM/16, 128>>>(atom_fea, p_ewt, emb_b, p_af, p_afh, p_afl);
    // slot 3: conv0 per-atom GEMMs
    k_mma_atom<<<dim3(4, NSTILES), 256, ATOM_SMEM>>>(p_afh, p_afl, p_wh, p_y, p_z);
    // slot 4: conv0 main GEMM  <-- profiled by ncu
    k_mma<<<dim3(2, NTILES), 256, MAIN_SMEM>>>(p_nfh, p_nfl, p_wh, p_y, p_z,
                                               nbr_idx, convs_b, convs_b + 128,
                                               p_g, p_stats);
    k_distance<<<(NM + 255)/256, 256>>>(atom_pos, nbr_off, cells, nbr_idx, p_dist);

    // --- conv layers ---
    for (int i = 0; i < NCONV; ++i){
        if (i > 0){
            k_zero<<<3, 256>>>(p_stats, 768);
            k_mma_atom<<<dim3(4, NSTILES), 256, ATOM_SMEM>>>(p_afh, p_afl,
                                                             p_wh + (size_t)i*NCHUNKS*16384, p_y, p_z);
            k_mma<<<dim3(2, NTILES), 256, MAIN_SMEM>>>(p_nfh, p_nfl,
                                                       p_wh + (size_t)i*NCHUNKS*16384, p_y, p_z,
                                                       nbr_idx, convs_b + i*256, convs_b + i*256 + 128,
                                                       p_g, p_stats);
        }
        k_gate_sum<<<NATOM/2, 256>>>(p_g, p_stats, bn1_g + i*256, bn1_b + i*256, p_s);
        k_colstats<<<NATOM/200, 128>>>(p_s, p_stats + 512);
        k_af_update<<<(NATOM*128 + 255)/256, 256>>>(p_af, p_s, p_stats + 512,
                                                    bn2_g + i*128, bn2_b + i*128, p_afh, p_afl);
    }

    // --- heads ---
    k_zero<<<2, 256>>>(p_stats, 512);
    k_mma_atom<<<dim3(4, NSTILES), 256, ATOM_SMEM>>>(p_afh, p_afl,
                                                     p_wh + (size_t)3*NCHUNKS*16384, p_y, p_z);
    k_mma<<<dim3(2, NTILES), 256, MAIN_SMEM>>>(p_nfh, p_nfl,
                                               p_wh + (size_t)3*NCHUNKS*16384, p_y, p_z,
                                               nbr_idx, dist_b, const_b, p_g, p_stats);
    k_head_final<<<NM/8, 256>>>(p_g, p_stats,
                                dbn_g, dbn_b, cbn_g, cbn_b,
                                d2W, d2b, c2W, c2b, p_dist, out);
}